// round 9
// baseline (speedup 1.0000x reference)
#include <cuda_runtime.h>

#define NBLK 128
#define NTHR 256

#define BB   32
#define TT   128
#define DD   16
#define HH   256
#define OSZ  8
#define NWIN 120
#define NSTEPS 127
#define TRAJ_BS (TT*DD)     /* 2048 */
#define OUT_BS  (NWIN*OSZ)  /* 960  */
#define HN_OFF  30720
#define CN_OFF  47104

// -------- persistent device state (no allocations allowed) --------
__device__ float gH0[2][8][BB][HH];   // [parity][slot][b][u] layer-0 hidden, ping-pong
__device__ float gH1[2][8][BB][HH];   // layer-1 hidden
__device__ unsigned g_barc = 0;
__device__ volatile unsigned g_barg = 0;

// -------- helpers --------
__device__ __forceinline__ unsigned long long pack2(float x, float y) {
    unsigned long long r;
    asm("mov.b64 %0, {%1, %2};" : "=l"(r) : "f"(x), "f"(y));
    return r;
}
__device__ __forceinline__ float2 unpack2(unsigned long long v) {
    float2 r;
    asm("mov.b64 {%0, %1}, %2;" : "=f"(r.x), "=f"(r.y) : "l"(v));
    return r;
}
__device__ __forceinline__ void fma2(unsigned long long& d, unsigned long long a,
                                     unsigned long long b) {
    asm("fma.rn.f32x2 %0, %1, %2, %0;" : "+l"(d) : "l"(a), "l"(b));
}
__device__ __forceinline__ float sigf(float x) { return 1.0f / (1.0f + __expf(-x)); }

__device__ __forceinline__ void grid_bar() {
    __syncthreads();
    if (threadIdx.x == 0) {
        unsigned old = g_barg;
        __threadfence();                       // release prior writes
        if (atomicAdd(&g_barc, 1u) == NBLK - 1) {
            atomicExch(&g_barc, 0u);           // reset before generation bump
            __threadfence();
            g_barg = old + 1u;
        } else {
            while (g_barg == old) __nanosleep(64);
            __threadfence();                   // acquire
        }
    }
    __syncthreads();
}

// K=128 chunk GEMM: acc[g][j] += sH[b0+j, :] . W[gate row, :] using packed f32x2.
__device__ __forceinline__ void gemm128(unsigned long long acc[4][2],
                                        const float* __restrict__ sH,
                                        const float* __restrict__ wbase,
                                        int ul, int b0)
{
    const ulonglong2* H0 = (const ulonglong2*)(sH + b0 * 132);
    const ulonglong2* H1 = (const ulonglong2*)(sH + (b0 + 1) * 132);
    const float* w0 = wbase + (ul * 4 + 0) * 260;
    const float* w1 = wbase + (ul * 4 + 1) * 260;
    const float* w2 = wbase + (ul * 4 + 2) * 260;
    const float* w3 = wbase + (ul * 4 + 3) * 260;
#pragma unroll 4
    for (int q = 0; q < 32; ++q) {
        ulonglong2 ha = H0[q];
        ulonglong2 hb = H1[q];
        ulonglong2 wa = *(const ulonglong2*)(w0 + q * 4);
        fma2(acc[0][0], ha.x, wa.x); fma2(acc[0][0], ha.y, wa.y);
        fma2(acc[0][1], hb.x, wa.x); fma2(acc[0][1], hb.y, wa.y);
        ulonglong2 wbq = *(const ulonglong2*)(w1 + q * 4);
        fma2(acc[1][0], ha.x, wbq.x); fma2(acc[1][0], ha.y, wbq.y);
        fma2(acc[1][1], hb.x, wbq.x); fma2(acc[1][1], hb.y, wbq.y);
        ulonglong2 wc = *(const ulonglong2*)(w2 + q * 4);
        fma2(acc[2][0], ha.x, wc.x); fma2(acc[2][0], ha.y, wc.y);
        fma2(acc[2][1], hb.x, wc.x); fma2(acc[2][1], hb.y, wc.y);
        ulonglong2 wd = *(const ulonglong2*)(w3 + q * 4);
        fma2(acc[3][0], ha.x, wd.x); fma2(acc[3][0], ha.y, wd.y);
        fma2(acc[3][1], hb.x, wd.x); fma2(acc[3][1], hb.y, wd.y);
    }
}

__global__ void __launch_bounds__(NTHR, 1)
orlstm_kernel(const float* __restrict__ traj,
              const float* __restrict__ Wih0, const float* __restrict__ Whh0,
              const float* __restrict__ bih0, const float* __restrict__ bhh0,
              const float* __restrict__ Wih1, const float* __restrict__ Whh1,
              const float* __restrict__ bih1, const float* __restrict__ bhh1,
              const float* __restrict__ Wlin, const float* __restrict__ blin,
              float* __restrict__ outp)
{
    extern __shared__ float smem[];
    float* sWhh0 = smem;                    // 64 rows x 260 (padded K=256)
    float* sWih1 = sWhh0 + 64 * 260;
    float* sWhh1 = sWih1 + 64 * 260;
    float* sWih0 = sWhh1 + 64 * 260;        // 64 rows x 20 (padded K=16)
    float* sB0   = sWih0 + 64 * 20;         // 64
    float* sB1   = sB0 + 64;                // 64
    float* sX    = sB1 + 64;                // 32 x 16
    float* sH    = sX + 32 * 16;            // 32 x 132 (also pred scratch 16x32x8)

    const int tid   = threadIdx.x;
    const int us    = blockIdx.x & 15;      // unit-slice 0..15
    const int wg    = blockIdx.x >> 4;      // window slot 0..7
    const int ubase = us * 16;
    const int ul    = tid & 15;             // local unit 0..15
    const int bg    = tid >> 4;             // batch group 0..15
    const int b0    = bg * 2;
    const int u     = ubase + ul;

    // ---- load this CTA's weight slices into smem (once per launch) ----
    for (int i = tid; i < 64 * 64; i += NTHR) {
        int rl = i >> 6, c4 = i & 63;
        int uu = rl >> 2, gg = rl & 3;
        int grow = gg * 256 + ubase + uu;
        *(float4*)(sWhh0 + (uu * 4 + gg) * 260 + c4 * 4) =
            __ldg((const float4*)(Whh0 + grow * 256) + c4);
        *(float4*)(sWih1 + (uu * 4 + gg) * 260 + c4 * 4) =
            __ldg((const float4*)(Wih1 + grow * 256) + c4);
        *(float4*)(sWhh1 + (uu * 4 + gg) * 260 + c4 * 4) =
            __ldg((const float4*)(Whh1 + grow * 256) + c4);
    }
    for (int i = tid; i < 64 * 4; i += NTHR) {
        int rl = i >> 2, c4 = i & 3;
        int uu = rl >> 2, gg = rl & 3;
        int grow = gg * 256 + ubase + uu;
        *(float4*)(sWih0 + (uu * 4 + gg) * 20 + c4 * 4) =
            __ldg((const float4*)(Wih0 + grow * 16) + c4);
    }
    for (int i = tid; i < 64; i += NTHR) {
        int uu = i >> 2, gg = i & 3;
        int grow = gg * 256 + ubase + uu;
        sB0[i] = __ldg(bih0 + grow) + __ldg(bhh0 + grow);
        sB1[i] = __ldg(bih1 + grow) + __ldg(bhh1 + grow);
    }
    __syncthreads();

    float c0r0 = 0.f, c0r1 = 0.f, c1r0 = 0.f, c1r1 = 0.f;  // cell state in registers

    for (int k = 0; k < NSTEPS; ++k) {
        const int p = k & 1;
        const int s = (k - wg + 8) & 7;   // this slot's step index at macro-step k
        const int t = k - s;              // window id in this slot
        const bool active = (t >= 0) && (t < NWIN);

        // ---------------- PHASE A: layer-0 cell ----------------
        // out[tf] base init (= out[tf-1] + b_lin); pred partials add in phase B.
        if (blockIdx.x == 0 && k >= 7) {
            int tf = k - 7;
            int b = tid >> 3, o = tid & 7;
            float base = (tf == 0)
                ? __ldg(traj + b * TRAJ_BS + 7 * DD + OSZ + o)
                : __ldcg(outp + b * OUT_BS + (tf - 1) * OSZ + o);
            outp[b * OUT_BS + tf * OSZ + o] = base + __ldg(blin + o);
        }

        if (active) {
            // build x input [32][16]
            for (int i = tid; i < 32 * 16; i += NTHR) {
                int b = i >> 4, col = i & 15;
                float v;
                if (col < 8) {
                    int idx = (t >= 1 && t <= 7 && s >= 8 - t) ? (2 * t + s - 1) : (t + s);
                    v = __ldg(traj + b * TRAJ_BS + idx * DD + col);
                } else {
                    int j = t + s - 8;
                    if (t >= 1 && j >= 0)
                        v = __ldcg(outp + b * OUT_BS + j * OSZ + (col - 8));
                    else
                        v = __ldg(traj + b * TRAJ_BS + (t + s) * DD + col);
                }
                sX[i] = v;
            }
            __syncthreads();

            unsigned long long acc[4][2];
#pragma unroll
            for (int g = 0; g < 4; ++g) {
                unsigned long long bz = pack2(sB0[ul * 4 + g], 0.f);
                acc[g][0] = bz; acc[g][1] = bz;
            }
            // x part (K=16)
            {
                const ulonglong2* X0 = (const ulonglong2*)(sX + b0 * 16);
                const ulonglong2* X1 = (const ulonglong2*)(sX + (b0 + 1) * 16);
#pragma unroll
                for (int q = 0; q < 4; ++q) {
                    ulonglong2 ha = X0[q], hb = X1[q];
#pragma unroll
                    for (int g = 0; g < 4; ++g) {
                        ulonglong2 w = *(const ulonglong2*)(sWih0 + (ul * 4 + g) * 20 + q * 4);
                        fma2(acc[g][0], ha.x, w.x); fma2(acc[g][0], ha.y, w.y);
                        fma2(acc[g][1], hb.x, w.x); fma2(acc[g][1], hb.y, w.y);
                    }
                }
            }
            // h0_old part (K=256, two chunks) — skipped at s==0 (h0_old == 0)
            if (s > 0) {
                const float* src = &gH0[p][wg][0][0];
#pragma unroll
                for (int c = 0; c < 2; ++c) {
                    __syncthreads();
                    for (int i = tid; i < 1024; i += NTHR) {
                        int b = i >> 5, q = i & 31;
                        *(float4*)(sH + b * 132 + q * 4) =
                            __ldcg((const float4*)(src + b * HH + c * 128) + q);
                    }
                    __syncthreads();
                    gemm128(acc, sH, sWhh0 + c * 128, ul, b0);
                }
            }
            // cell update layer 0
            float* dstH = &gH0[p ^ 1][wg][0][0];
#pragma unroll
            for (int j = 0; j < 2; ++j) {
                int b = b0 + j;
                float2 r0 = unpack2(acc[0][j]); float gi = r0.x + r0.y;
                float2 r1 = unpack2(acc[1][j]); float gf = r1.x + r1.y;
                float2 r2 = unpack2(acc[2][j]); float gG = r2.x + r2.y;
                float2 r3 = unpack2(acc[3][j]); float gO = r3.x + r3.y;
                float cold = j ? c0r1 : c0r0;
                float cn = (s ? sigf(gf) * cold : 0.f) + sigf(gi) * tanhf(gG);
                if (j) c0r1 = cn; else c0r0 = cn;
                float hn = sigf(gO) * tanhf(cn);
                __stcg(dstH + b * HH + u, hn);
                if (t == NWIN - 1 && s == 7) {
                    outp[HN_OFF + b * HH + u] = hn;
                    outp[CN_OFF + b * HH + u] = cn;
                }
            }
        }
        grid_bar();

        // ---------------- PHASE B: layer-1 cell (+ pred for finishing window) ----
        if (active) {
            unsigned long long acc[4][2];
#pragma unroll
            for (int g = 0; g < 4; ++g) {
                unsigned long long bz = pack2(sB1[ul * 4 + g], 0.f);
                acc[g][0] = bz; acc[g][1] = bz;
            }
            const float* srcA = &gH0[p ^ 1][wg][0][0];  // h0_new (this macro-step)
            const float* srcB = &gH1[p][wg][0][0];      // h1_old
            const int nch = (s > 0) ? 4 : 2;            // skip h1_old chunks at s==0
            for (int c = 0; c < nch; ++c) {
                const float* src = (c < 2) ? (srcA + c * 128) : (srcB + (c - 2) * 128);
                const float* wb  = (c < 2) ? (sWih1 + c * 128) : (sWhh1 + (c - 2) * 128);
                __syncthreads();
                for (int i = tid; i < 1024; i += NTHR) {
                    int b = i >> 5, q = i & 31;
                    *(float4*)(sH + b * 132 + q * 4) =
                        __ldcg((const float4*)(src + b * HH) + q);
                }
                __syncthreads();
                gemm128(acc, sH, wb, ul, b0);
            }
            float* dstH = &gH1[p ^ 1][wg][0][0];
            float h1v0 = 0.f, h1v1 = 0.f;
#pragma unroll
            for (int j = 0; j < 2; ++j) {
                int b = b0 + j;
                float2 r0 = unpack2(acc[0][j]); float gi = r0.x + r0.y;
                float2 r1 = unpack2(acc[1][j]); float gf = r1.x + r1.y;
                float2 r2 = unpack2(acc[2][j]); float gG = r2.x + r2.y;
                float2 r3 = unpack2(acc[3][j]); float gO = r3.x + r3.y;
                float cold = j ? c1r1 : c1r0;
                float cn = (s ? sigf(gf) * cold : 0.f) + sigf(gi) * tanhf(gG);
                if (j) c1r1 = cn; else c1r0 = cn;
                float hn = sigf(gO) * tanhf(cn);
                if (j) h1v1 = hn; else h1v0 = hn;
                __stcg(dstH + b * HH + u, hn);
                if (t == NWIN - 1 && s == 7) {
                    outp[HN_OFF + BB * HH + b * HH + u] = hn;
                    outp[CN_OFF + BB * HH + b * HH + u] = cn;
                }
            }
            // finishing window: pred = h1T @ Wlin.T, reduce in smem, one atomic per (b,o)
            if (s == 7) {
                __syncthreads();               // sH gemm reads done; reuse as scratch
#pragma unroll
                for (int j = 0; j < 2; ++j) {
                    int b = b0 + j;
                    float hv = j ? h1v1 : h1v0;
#pragma unroll
                    for (int o = 0; o < 8; ++o)
                        sH[(ul * 32 + b) * 8 + o] = hv * __ldg(Wlin + o * HH + u);
                }
                __syncthreads();
                int b = tid >> 3, o = tid & 7;
                float ssum = 0.f;
#pragma unroll
                for (int i2 = 0; i2 < 16; ++i2) ssum += sH[(i2 * 32 + b) * 8 + o];
                atomicAdd(outp + b * OUT_BS + t * OSZ + o, ssum);
            }
        }
        grid_bar();
    }
}

extern "C" void kernel_launch(void* const* d_in, const int* in_sizes, int n_in,
                              void* d_out, int out_size)
{
    (void)in_sizes; (void)n_in; (void)out_size;
    const size_t smem_bytes = 56064 * sizeof(float);  // 224256 B
    cudaFuncSetAttribute(orlstm_kernel,
                         cudaFuncAttributeMaxDynamicSharedMemorySize,
                         (int)smem_bytes);
    orlstm_kernel<<<NBLK, NTHR, smem_bytes>>>(
        (const float*)d_in[0],
        (const float*)d_in[1], (const float*)d_in[2],
        (const float*)d_in[3], (const float*)d_in[4],
        (const float*)d_in[5], (const float*)d_in[6],
        (const float*)d_in[7], (const float*)d_in[8],
        (const float*)d_in[9], (const float*)d_in[10],
        (float*)d_out);
}

// round 10
// speedup vs baseline: 2.5862x; 2.5862x over previous
#include <cuda_runtime.h>

#define NBLK 128
#define NTHR 128

#define BB   32
#define TT   128
#define DD   16
#define HH   256
#define OSZ  8
#define NWIN 120
#define NSTEPS 127
#define TRAJ_BS (TT*DD)     /* 2048 */
#define OUT_BS  (NWIN*OSZ)  /* 960  */
#define HN_OFF  30720
#define CN_OFF  47104

typedef unsigned long long ull;

// -------- persistent device state (no allocations allowed) --------
__device__ float gH0[2][8][BB][HH];   // [parity][slot][b][u] layer-0 hidden, ping-pong
__device__ float gH1[2][8][BB][HH];   // layer-1 hidden
__device__ unsigned g_barc = 0;
__device__ volatile unsigned g_barg = 0;

// -------- helpers --------
__device__ __forceinline__ ull pack2(float x, float y) {
    ull r; asm("mov.b64 %0, {%1, %2};" : "=l"(r) : "f"(x), "f"(y)); return r;
}
__device__ __forceinline__ float2 unpack2(ull v) {
    float2 r; asm("mov.b64 {%0, %1}, %2;" : "=f"(r.x), "=f"(r.y) : "l"(v)); return r;
}
__device__ __forceinline__ void fma2(ull& d, ull a, ull b) {
    asm("fma.rn.f32x2 %0, %1, %2, %0;" : "+l"(d) : "l"(a), "l"(b));
}
__device__ __forceinline__ float sigf(float x) { return 1.0f / (1.0f + __expf(-x)); }
__device__ __forceinline__ float sum2(ull v) { float2 f = unpack2(v); return f.x + f.y; }

__device__ __forceinline__ void grid_bar() {
    __threadfence();            // every thread drains its global stores to L2
    __syncthreads();
    if (threadIdx.x == 0) {
        unsigned old = g_barg;
        if (atomicAdd(&g_barc, 1u) == NBLK - 1) {
            atomicExch(&g_barc, 0u);
            __threadfence();
            g_barg = old + 1u;
        } else {
            while (g_barg == old) __nanosleep(32);
            __threadfence();
        }
    }
    __syncthreads();
}

// ---- K=128 chunk GEMM. sH: [32][128] row-major. sW layout per k2 row (128 fl):
// sW[k2*128 + (g>>1)*64 + ul*4 + (g&1)*2 + e] = W[g,u][2*k2+e]. Conflict-free. ----
__device__ __forceinline__ void gemm128(ull acc[4][4],
                                        const float* __restrict__ sH,
                                        const float* __restrict__ sW,
                                        int ul, int b0)
{
    const float* hp = sH + b0 * 128;
    const float* wp = sW + ul * 4;
#pragma unroll 2
    for (int q = 0; q < 32; ++q) {
        ulonglong2 h0 = *(const ulonglong2*)(hp + 0 * 128 + q * 4);
        ulonglong2 h1 = *(const ulonglong2*)(hp + 1 * 128 + q * 4);
        ulonglong2 h2 = *(const ulonglong2*)(hp + 2 * 128 + q * 4);
        ulonglong2 h3 = *(const ulonglong2*)(hp + 3 * 128 + q * 4);
        {
            const float* w = wp + (2 * q) * 128;
            ulonglong2 wA = *(const ulonglong2*)(w);
            ulonglong2 wB = *(const ulonglong2*)(w + 64);
            fma2(acc[0][0], h0.x, wA.x); fma2(acc[0][1], h1.x, wA.x);
            fma2(acc[0][2], h2.x, wA.x); fma2(acc[0][3], h3.x, wA.x);
            fma2(acc[1][0], h0.x, wA.y); fma2(acc[1][1], h1.x, wA.y);
            fma2(acc[1][2], h2.x, wA.y); fma2(acc[1][3], h3.x, wA.y);
            fma2(acc[2][0], h0.x, wB.x); fma2(acc[2][1], h1.x, wB.x);
            fma2(acc[2][2], h2.x, wB.x); fma2(acc[2][3], h3.x, wB.x);
            fma2(acc[3][0], h0.x, wB.y); fma2(acc[3][1], h1.x, wB.y);
            fma2(acc[3][2], h2.x, wB.y); fma2(acc[3][3], h3.x, wB.y);
        }
        {
            const float* w = wp + (2 * q + 1) * 128;
            ulonglong2 wA = *(const ulonglong2*)(w);
            ulonglong2 wB = *(const ulonglong2*)(w + 64);
            fma2(acc[0][0], h0.y, wA.x); fma2(acc[0][1], h1.y, wA.x);
            fma2(acc[0][2], h2.y, wA.x); fma2(acc[0][3], h3.y, wA.x);
            fma2(acc[1][0], h0.y, wA.y); fma2(acc[1][1], h1.y, wA.y);
            fma2(acc[1][2], h2.y, wA.y); fma2(acc[1][3], h3.y, wA.y);
            fma2(acc[2][0], h0.y, wB.x); fma2(acc[2][1], h1.y, wB.x);
            fma2(acc[2][2], h2.y, wB.x); fma2(acc[2][3], h3.y, wB.x);
            fma2(acc[3][0], h0.y, wB.y); fma2(acc[3][1], h1.y, wB.y);
            fma2(acc[3][2], h2.y, wB.y); fma2(acc[3][3], h3.y, wB.y);
        }
    }
}

// K=16 x-part GEMM over sX [32][16]
__device__ __forceinline__ void gemm16(ull acc[4][4],
                                       const float* __restrict__ sX,
                                       const float* __restrict__ sW,
                                       int ul, int b0)
{
    const float* hp = sX + b0 * 16;
    const float* wp = sW + ul * 4;
#pragma unroll
    for (int q = 0; q < 4; ++q) {
        ulonglong2 h0 = *(const ulonglong2*)(hp + 0 * 16 + q * 4);
        ulonglong2 h1 = *(const ulonglong2*)(hp + 1 * 16 + q * 4);
        ulonglong2 h2 = *(const ulonglong2*)(hp + 2 * 16 + q * 4);
        ulonglong2 h3 = *(const ulonglong2*)(hp + 3 * 16 + q * 4);
#pragma unroll
        for (int e = 0; e < 2; ++e) {
            const float* w = wp + (2 * q + e) * 128;
            ulonglong2 wA = *(const ulonglong2*)(w);
            ulonglong2 wB = *(const ulonglong2*)(w + 64);
            ull v0 = e ? h0.y : h0.x, v1 = e ? h1.y : h1.x;
            ull v2 = e ? h2.y : h2.x, v3 = e ? h3.y : h3.x;
            fma2(acc[0][0], v0, wA.x); fma2(acc[0][1], v1, wA.x);
            fma2(acc[0][2], v2, wA.x); fma2(acc[0][3], v3, wA.x);
            fma2(acc[1][0], v0, wA.y); fma2(acc[1][1], v1, wA.y);
            fma2(acc[1][2], v2, wA.y); fma2(acc[1][3], v3, wA.y);
            fma2(acc[2][0], v0, wB.x); fma2(acc[2][1], v1, wB.x);
            fma2(acc[2][2], v2, wB.x); fma2(acc[2][3], v3, wB.x);
            fma2(acc[3][0], v0, wB.y); fma2(acc[3][1], v1, wB.y);
            fma2(acc[3][2], v2, wB.y); fma2(acc[3][3], v3, wB.y);
        }
    }
}

// Prefetch one 32x128 chunk (global, L2) into registers; store into sH.
__device__ __forceinline__ void ldg_chunk(float4 r[8], const float* __restrict__ src, int tid) {
#pragma unroll
    for (int j = 0; j < 8; ++j) {
        int idx = tid + j * NTHR;
        int b = idx >> 5, q = idx & 31;
        r[j] = __ldcg((const float4*)(src + b * HH) + q);
    }
}
__device__ __forceinline__ void sts_chunk(const float4 r[8], float* __restrict__ sH, int tid) {
#pragma unroll
    for (int j = 0; j < 8; ++j) {
        int idx = tid + j * NTHR;
        *(float4*)(sH + idx * 4) = r[j];
    }
}

// Stage one 64-row x 256-k weight slice into the k-major interleaved layout.
__device__ __forceinline__ void stage_w256(const float* __restrict__ src,
                                           float* __restrict__ dst,
                                           int ubase, int tid)
{
    for (int i = tid; i < 8192; i += NTHR) {
        int r = i >> 7, k2 = i & 127;
        int uu = r >> 2, g = r & 3;
        int grow = g * 256 + ubase + uu;
        float2 w = __ldg((const float2*)(src + grow * 256 + 2 * k2));
        int doff = k2 * 128 + (g >> 1) * 64 + uu * 4 + (g & 1) * 2;
        dst[doff] = w.x; dst[doff + 1] = w.y;
    }
}

__global__ void __launch_bounds__(NTHR, 1)
orlstm_kernel(const float* __restrict__ traj,
              const float* __restrict__ Wih0, const float* __restrict__ Whh0,
              const float* __restrict__ bih0, const float* __restrict__ bhh0,
              const float* __restrict__ Wih1, const float* __restrict__ Whh1,
              const float* __restrict__ bih1, const float* __restrict__ bhh1,
              const float* __restrict__ Wlin, const float* __restrict__ blin,
              float* __restrict__ outp)
{
    extern __shared__ float smem[];
    float* sWhh0 = smem;                    // 128 k2 x 128 = 16384 fl
    float* sWih1 = sWhh0 + 16384;
    float* sWhh1 = sWih1 + 16384;
    float* sWih0 = sWhh1 + 16384;           // 8 k2 x 128 = 1024 fl
    float* sB0   = sWih0 + 1024;            // 64
    float* sB1   = sB0 + 64;                // 64
    float* sX    = sB1 + 64;                // 32 x 16
    float* sH    = sX + 512;                // 32 x 128 = 4096 fl
    // total 54912 floats = 219648 B

    const int tid   = threadIdx.x;
    const int us    = blockIdx.x & 15;      // unit-slice 0..15
    const int wg    = blockIdx.x >> 4;      // window slot 0..7
    const int ubase = us * 16;
    const int ul    = tid & 15;             // local unit 0..15
    const int bq    = tid >> 4;             // batch quad 0..7
    const int b0    = bq * 4;
    const int u     = ubase + ul;

    // ---- one-time weight staging ----
    stage_w256(Whh0, sWhh0, ubase, tid);
    stage_w256(Wih1, sWih1, ubase, tid);
    stage_w256(Whh1, sWhh1, ubase, tid);
    for (int i = tid; i < 512; i += NTHR) {
        int r = i >> 3, k2 = i & 7;
        int uu = r >> 2, g = r & 3;
        int grow = g * 256 + ubase + uu;
        float2 w = __ldg((const float2*)(Wih0 + grow * 16 + 2 * k2));
        int doff = k2 * 128 + (g >> 1) * 64 + uu * 4 + (g & 1) * 2;
        sWih0[doff] = w.x; sWih0[doff + 1] = w.y;
    }
    if (tid < 64) {
        int uu = tid >> 2, g = tid & 3;
        int grow = g * 256 + ubase + uu;
        sB0[uu * 4 + g] = __ldg(bih0 + grow) + __ldg(bhh0 + grow);
        sB1[uu * 4 + g] = __ldg(bih1 + grow) + __ldg(bhh1 + grow);
    }
    __syncthreads();

    float c0s[4] = {0.f, 0.f, 0.f, 0.f};   // cell state, layer 0 (4 batches)
    float c1s[4] = {0.f, 0.f, 0.f, 0.f};   // cell state, layer 1

    for (int k = 0; k < NSTEPS; ++k) {
        const int p = k & 1;
        const int s = (k - wg + 8) & 7;     // this slot's step index at macro-step k
        const int t = k - s;                // window id in this slot
        const bool active = (t >= 0) && (t < NWIN);

        // ---------------- PHASE A: layer-0 cell ----------------
        // out[tf] base init (= out[tf-1] + b_lin); pred partials added in phase B.
        if (blockIdx.x == 0 && k >= 7) {
            int tf = k - 7;
            for (int e = tid; e < 256; e += NTHR) {
                int b = e >> 3, o = e & 7;
                float base = (tf == 0)
                    ? __ldg(traj + b * TRAJ_BS + 7 * DD + OSZ + o)
                    : __ldcg(outp + b * OUT_BS + (tf - 1) * OSZ + o);
                outp[b * OUT_BS + tf * OSZ + o] = base + __ldg(blin + o);
            }
        }

        ull acc[4][4];
        float hn1[4];

        if (active) {
            // build x input [32][16]
            for (int i = tid; i < 512; i += NTHR) {
                int b = i >> 4, col = i & 15;
                float v;
                if (col < 8) {
                    int idx = (t >= 1 && t <= 7 && s >= 8 - t) ? (2 * t + s - 1) : (t + s);
                    v = __ldg(traj + b * TRAJ_BS + idx * DD + col);
                } else {
                    int j = t + s - 8;
                    if (t >= 1 && j >= 0)
                        v = __ldcg(outp + b * OUT_BS + j * OSZ + (col - 8));
                    else
                        v = __ldg(traj + b * TRAJ_BS + (t + s) * DD + col);
                }
                sX[i] = v;
            }
            __syncthreads();

#pragma unroll
            for (int g = 0; g < 4; ++g) {
                ull bz = pack2(sB0[ul * 4 + g], 0.f);
#pragma unroll
                for (int j = 0; j < 4; ++j) acc[g][j] = bz;
            }
            gemm16(acc, sX, sWih0, ul, b0);

            if (s > 0) {                    // h0_old part (K=256), skipped at s==0
                const float* src = &gH0[p][wg][0][0];
                float4 r[8];
                ldg_chunk(r, src, tid);
#pragma unroll
                for (int c = 0; c < 2; ++c) {
                    __syncthreads();
                    sts_chunk(r, sH, tid);
                    __syncthreads();
                    if (c == 0) ldg_chunk(r, src + 128, tid);
                    gemm128(acc, sH, sWhh0 + c * 8192, ul, b0);
                }
            }
            // cell update layer 0
            float* dstH = &gH0[p ^ 1][wg][0][0];
#pragma unroll
            for (int j = 0; j < 4; ++j) {
                int b = b0 + j;
                float gi = sum2(acc[0][j]);
                float gf = sum2(acc[1][j]);
                float gG = sum2(acc[2][j]);
                float gO = sum2(acc[3][j]);
                float cn = (s ? sigf(gf) * c0s[j] : 0.f) + sigf(gi) * tanhf(gG);
                c0s[j] = cn;
                float hn = sigf(gO) * tanhf(cn);
                __stcg(dstH + b * HH + u, hn);
                if (t == NWIN - 1 && s == 7) {
                    outp[HN_OFF + b * HH + u] = hn;
                    outp[CN_OFF + b * HH + u] = cn;
                }
            }
        }
        grid_bar();

        // ---------------- PHASE B: layer-1 cell (+ pred for finishing window) ----
        if (active) {
#pragma unroll
            for (int g = 0; g < 4; ++g) {
                ull bz = pack2(sB1[ul * 4 + g], 0.f);
#pragma unroll
                for (int j = 0; j < 4; ++j) acc[g][j] = bz;
            }
            const float* srcA = &gH0[p ^ 1][wg][0][0];  // h0_new (this macro-step)
            const float* srcB = &gH1[p][wg][0][0];      // h1_old
            const int nch = (s > 0) ? 4 : 2;
            float4 r[8];
            ldg_chunk(r, srcA, tid);
            for (int c = 0; c < nch; ++c) {
                __syncthreads();
                sts_chunk(r, sH, tid);
                __syncthreads();
                if (c + 1 < nch) {
                    const float* nsrc = (c + 1 < 2) ? (srcA + (c + 1) * 128)
                                                    : (srcB + (c - 1) * 128);
                    ldg_chunk(r, nsrc, tid);
                }
                const float* wb = (c < 2) ? (sWih1 + c * 8192)
                                          : (sWhh1 + (c - 2) * 8192);
                gemm128(acc, sH, wb, ul, b0);
            }
            float* dstH = &gH1[p ^ 1][wg][0][0];
#pragma unroll
            for (int j = 0; j < 4; ++j) {
                int b = b0 + j;
                float gi = sum2(acc[0][j]);
                float gf = sum2(acc[1][j]);
                float gG = sum2(acc[2][j]);
                float gO = sum2(acc[3][j]);
                float cn = (s ? sigf(gf) * c1s[j] : 0.f) + sigf(gi) * tanhf(gG);
                c1s[j] = cn;
                float hn = sigf(gO) * tanhf(cn);
                hn1[j] = hn;
                __stcg(dstH + b * HH + u, hn);
                if (t == NWIN - 1 && s == 7) {
                    outp[HN_OFF + BB * HH + b * HH + u] = hn;
                    outp[CN_OFF + BB * HH + b * HH + u] = cn;
                }
            }
            // finishing window: pred = h1T @ Wlin.T via shfl reduction over ul lanes
            if (s == 7) {
                float wl[8];
#pragma unroll
                for (int o = 0; o < 8; ++o) wl[o] = __ldg(Wlin + o * HH + u);
#pragma unroll
                for (int j = 0; j < 4; ++j) {
#pragma unroll
                    for (int o = 0; o < 8; ++o) {
                        float v = hn1[j] * wl[o];
                        v += __shfl_xor_sync(0xffffffffu, v, 1);
                        v += __shfl_xor_sync(0xffffffffu, v, 2);
                        v += __shfl_xor_sync(0xffffffffu, v, 4);
                        v += __shfl_xor_sync(0xffffffffu, v, 8);
                        if (ul == 0)
                            atomicAdd(outp + (b0 + j) * OUT_BS + t * OSZ + o, v);
                    }
                }
            }
        }
        grid_bar();
    }
}

extern "C" void kernel_launch(void* const* d_in, const int* in_sizes, int n_in,
                              void* d_out, int out_size)
{
    (void)in_sizes; (void)n_in; (void)out_size;
    const size_t smem_bytes = 54912 * sizeof(float);  // 219648 B
    cudaFuncSetAttribute(orlstm_kernel,
                         cudaFuncAttributeMaxDynamicSharedMemorySize,
                         (int)smem_bytes);
    orlstm_kernel<<<NBLK, NTHR, smem_bytes>>>(
        (const float*)d_in[0],
        (const float*)d_in[1], (const float*)d_in[2],
        (const float*)d_in[3], (const float*)d_in[4],
        (const float*)d_in[5], (const float*)d_in[6],
        (const float*)d_in[7], (const float*)d_in[8],
        (const float*)d_in[9], (const float*)d_in[10],
        (float*)d_out);
}

// round 11
// speedup vs baseline: 2.7937x; 1.0802x over previous
#include <cuda_runtime.h>

#define NBLK 128
#define NTHR 256

#define BB   32
#define TT   128
#define DD   16
#define HH   256
#define OSZ  8
#define NWIN 120
#define NSTEPS 127
#define TRAJ_BS (TT*DD)     /* 2048 */
#define OUT_BS  (NWIN*OSZ)  /* 960  */
#define HN_OFF  30720
#define CN_OFF  47104

typedef unsigned long long ull;

// -------- persistent device state (no allocations allowed) --------
__device__ float gH0[2][8][BB][HH];   // [parity][slot][b][u] layer-0 hidden, ping-pong
__device__ float gH1[2][8][BB][HH];   // layer-1 hidden
__device__ unsigned g_barc = 0;
__device__ volatile unsigned g_barg = 0;

// -------- helpers --------
__device__ __forceinline__ ull pack2(float x, float y) {
    ull r; asm("mov.b64 %0, {%1, %2};" : "=l"(r) : "f"(x), "f"(y)); return r;
}
__device__ __forceinline__ float2 unpack2(ull v) {
    float2 r; asm("mov.b64 {%0, %1}, %2;" : "=f"(r.x), "=f"(r.y) : "l"(v)); return r;
}
__device__ __forceinline__ void fma2(ull& d, ull a, ull b) {
    asm("fma.rn.f32x2 %0, %1, %2, %0;" : "+l"(d) : "l"(a), "l"(b));
}
__device__ __forceinline__ float sigf(float x) { return 1.0f / (1.0f + __expf(-x)); }
__device__ __forceinline__ float sum2(ull v) { float2 f = unpack2(v); return f.x + f.y; }

__device__ __forceinline__ void grid_bar() {
    __threadfence();            // drain global stores to L2
    __syncthreads();
    if (threadIdx.x == 0) {
        unsigned old = g_barg;
        if (atomicAdd(&g_barc, 1u) == NBLK - 1) {
            atomicExch(&g_barc, 0u);
            __threadfence();
            g_barg = old + 1u;
        } else {
            while (g_barg == old) __nanosleep(32);
            __threadfence();
        }
    }
    __syncthreads();
}

// ---- half-chunk GEMM (K=64 of a staged 128-chunk). sH: [32][128] row-major.
// sW chunk layout: 64 k2-rows x 128 fl; row r = k pair (2r,2r+1);
// within row: (g>>1)*64 + ul*4 + (g&1)*2 holds the f32x2 for (g,u) over that pair.
// kh=0 handles rows 0..31 (K 0..63), kh=1 rows 32..63 (K 64..127). ----
__device__ __forceinline__ void gemm64(ull acc[4][4],
                                       const float* __restrict__ sH,
                                       const float* __restrict__ sW,
                                       int ul, int b0, int kh)
{
    const float* hp = sH + b0 * 128 + kh * 64;
    const float* wp = sW + kh * 4096 + ul * 4;
#pragma unroll 4
    for (int q = 0; q < 16; ++q) {
        ulonglong2 h0 = *(const ulonglong2*)(hp + 0 * 128 + q * 4);
        ulonglong2 h1 = *(const ulonglong2*)(hp + 1 * 128 + q * 4);
        ulonglong2 h2 = *(const ulonglong2*)(hp + 2 * 128 + q * 4);
        ulonglong2 h3 = *(const ulonglong2*)(hp + 3 * 128 + q * 4);
        {
            const float* w = wp + (2 * q) * 128;
            ulonglong2 wA = *(const ulonglong2*)(w);
            ulonglong2 wB = *(const ulonglong2*)(w + 64);
            fma2(acc[0][0], h0.x, wA.x); fma2(acc[0][1], h1.x, wA.x);
            fma2(acc[0][2], h2.x, wA.x); fma2(acc[0][3], h3.x, wA.x);
            fma2(acc[1][0], h0.x, wA.y); fma2(acc[1][1], h1.x, wA.y);
            fma2(acc[1][2], h2.x, wA.y); fma2(acc[1][3], h3.x, wA.y);
            fma2(acc[2][0], h0.x, wB.x); fma2(acc[2][1], h1.x, wB.x);
            fma2(acc[2][2], h2.x, wB.x); fma2(acc[2][3], h3.x, wB.x);
            fma2(acc[3][0], h0.x, wB.y); fma2(acc[3][1], h1.x, wB.y);
            fma2(acc[3][2], h2.x, wB.y); fma2(acc[3][3], h3.x, wB.y);
        }
        {
            const float* w = wp + (2 * q + 1) * 128;
            ulonglong2 wA = *(const ulonglong2*)(w);
            ulonglong2 wB = *(const ulonglong2*)(w + 64);
            fma2(acc[0][0], h0.y, wA.x); fma2(acc[0][1], h1.y, wA.x);
            fma2(acc[0][2], h2.y, wA.x); fma2(acc[0][3], h3.y, wA.x);
            fma2(acc[1][0], h0.y, wA.y); fma2(acc[1][1], h1.y, wA.y);
            fma2(acc[1][2], h2.y, wA.y); fma2(acc[1][3], h3.y, wA.y);
            fma2(acc[2][0], h0.y, wB.x); fma2(acc[2][1], h1.y, wB.x);
            fma2(acc[2][2], h2.y, wB.x); fma2(acc[2][3], h3.y, wB.x);
            fma2(acc[3][0], h0.y, wB.y); fma2(acc[3][1], h1.y, wB.y);
            fma2(acc[3][2], h2.y, wB.y); fma2(acc[3][3], h3.y, wB.y);
        }
    }
}

// K=16 x-part GEMM over sX [32][16] (kh==0 warps only)
__device__ __forceinline__ void gemm16(ull acc[4][4],
                                       const float* __restrict__ sX,
                                       const float* __restrict__ sW,
                                       int ul, int b0)
{
    const float* hp = sX + b0 * 16;
    const float* wp = sW + ul * 4;
#pragma unroll
    for (int q = 0; q < 4; ++q) {
        ulonglong2 h0 = *(const ulonglong2*)(hp + 0 * 16 + q * 4);
        ulonglong2 h1 = *(const ulonglong2*)(hp + 1 * 16 + q * 4);
        ulonglong2 h2 = *(const ulonglong2*)(hp + 2 * 16 + q * 4);
        ulonglong2 h3 = *(const ulonglong2*)(hp + 3 * 16 + q * 4);
#pragma unroll
        for (int e = 0; e < 2; ++e) {
            const float* w = wp + (2 * q + e) * 128;
            ulonglong2 wA = *(const ulonglong2*)(w);
            ulonglong2 wB = *(const ulonglong2*)(w + 64);
            ull v0 = e ? h0.y : h0.x, v1 = e ? h1.y : h1.x;
            ull v2 = e ? h2.y : h2.x, v3 = e ? h3.y : h3.x;
            fma2(acc[0][0], v0, wA.x); fma2(acc[0][1], v1, wA.x);
            fma2(acc[0][2], v2, wA.x); fma2(acc[0][3], v3, wA.x);
            fma2(acc[1][0], v0, wA.y); fma2(acc[1][1], v1, wA.y);
            fma2(acc[1][2], v2, wA.y); fma2(acc[1][3], v3, wA.y);
            fma2(acc[2][0], v0, wB.x); fma2(acc[2][1], v1, wB.x);
            fma2(acc[2][2], v2, wB.x); fma2(acc[2][3], v3, wB.x);
            fma2(acc[3][0], v0, wB.y); fma2(acc[3][1], v1, wB.y);
            fma2(acc[3][2], v2, wB.y); fma2(acc[3][3], v3, wB.y);
        }
    }
}

// Prefetch one 32x128 chunk (global, L2) into registers; store into sH.
__device__ __forceinline__ void ldg_chunk(float4 r[4], const float* __restrict__ src, int tid) {
#pragma unroll
    for (int j = 0; j < 4; ++j) {
        int idx = tid + j * NTHR;
        int b = idx >> 5, q = idx & 31;
        r[j] = __ldcg((const float4*)(src + b * HH) + q);
    }
}
__device__ __forceinline__ void sts_chunk(const float4 r[4], float* __restrict__ sH, int tid) {
#pragma unroll
    for (int j = 0; j < 4; ++j) {
        int idx = tid + j * NTHR;
        *(float4*)(sH + idx * 4) = r[j];
    }
}

// Stage one 64-row x 256-k weight slice into the k-major interleaved layout.
__device__ __forceinline__ void stage_w256(const float* __restrict__ src,
                                           float* __restrict__ dst,
                                           int ubase, int tid)
{
    for (int i = tid; i < 8192; i += NTHR) {
        int r = i >> 7, k2 = i & 127;
        int uu = r >> 2, g = r & 3;
        int grow = g * 256 + ubase + uu;
        float2 w = __ldg((const float2*)(src + grow * 256 + 2 * k2));
        int doff = k2 * 128 + (g >> 1) * 64 + uu * 4 + (g & 1) * 2;
        dst[doff] = w.x; dst[doff + 1] = w.y;
    }
}

__global__ void __launch_bounds__(NTHR, 1)
orlstm_kernel(const float* __restrict__ traj,
              const float* __restrict__ Wih0, const float* __restrict__ Whh0,
              const float* __restrict__ bih0, const float* __restrict__ bhh0,
              const float* __restrict__ Wih1, const float* __restrict__ Whh1,
              const float* __restrict__ bih1, const float* __restrict__ bhh1,
              const float* __restrict__ Wlin, const float* __restrict__ blin,
              float* __restrict__ outp)
{
    extern __shared__ float smem[];
    float* sWhh0 = smem;                    // 128 k2 x 128 = 16384 fl
    float* sWih1 = sWhh0 + 16384;
    float* sWhh1 = sWih1 + 16384;
    float* sWih0 = sWhh1 + 16384;           // 8 k2 x 128 = 1024 fl
    float* sB0   = sWih0 + 1024;            // 64
    float* sB1   = sB0 + 64;                // 64
    float* sX    = sB1 + 64;                // 32 x 16
    float* sH    = sX + 512;                // 32 x 128 = 4096 fl (also kh reduction buf)
    // total 54912 floats = 219648 B

    const int tid   = threadIdx.x;
    const int us    = blockIdx.x & 15;      // unit-slice 0..15
    const int wg    = blockIdx.x >> 4;      // window slot 0..7
    const int ubase = us * 16;
    const int ul    = tid & 15;             // local unit 0..15
    const int bq    = (tid >> 4) & 7;       // batch quad 0..7
    const int kh    = tid >> 7;             // k-half: warps 0-3 -> 0, warps 4-7 -> 1
    const int t128  = tid & 127;
    const int b0    = bq * 4;
    const int u     = ubase + ul;

    // ---- one-time weight staging ----
    stage_w256(Whh0, sWhh0, ubase, tid);
    stage_w256(Wih1, sWih1, ubase, tid);
    stage_w256(Whh1, sWhh1, ubase, tid);
    for (int i = tid; i < 512; i += NTHR) {
        int r = i >> 3, k2 = i & 7;
        int uu = r >> 2, g = r & 3;
        int grow = g * 256 + ubase + uu;
        float2 w = __ldg((const float2*)(Wih0 + grow * 16 + 2 * k2));
        int doff = k2 * 128 + (g >> 1) * 64 + uu * 4 + (g & 1) * 2;
        sWih0[doff] = w.x; sWih0[doff + 1] = w.y;
    }
    if (tid < 64) {
        int uu = tid >> 2, g = tid & 3;
        int grow = g * 256 + ubase + uu;
        sB0[uu * 4 + g] = __ldg(bih0 + grow) + __ldg(bhh0 + grow);
        sB1[uu * 4 + g] = __ldg(bih1 + grow) + __ldg(bhh1 + grow);
    }
    __syncthreads();

    float c0s[4] = {0.f, 0.f, 0.f, 0.f};   // cell state (kh==0 threads only)
    float c1s[4] = {0.f, 0.f, 0.f, 0.f};

    for (int k = 0; k < NSTEPS; ++k) {
        const int p = k & 1;
        const int s = (k - wg + 8) & 7;     // this slot's step index at macro-step k
        const int t = k - s;                // window id in this slot
        const bool active = (t >= 0) && (t < NWIN);

        // ---------------- PHASE A: layer-0 cell ----------------
        if (blockIdx.x == 0 && k >= 7) {
            int tf = k - 7;
            int b = tid >> 3, o = tid & 7;
            if (tid < 256) {
                float base = (tf == 0)
                    ? __ldg(traj + b * TRAJ_BS + 7 * DD + OSZ + o)
                    : __ldcg(outp + b * OUT_BS + (tf - 1) * OSZ + o);
                outp[b * OUT_BS + tf * OSZ + o] = base + __ldg(blin + o);
            }
        }

        ull acc[4][4];
        float hn1[4];

        if (active) {
            // build x input [32][16]
            for (int i = tid; i < 512; i += NTHR) {
                int b = i >> 4, col = i & 15;
                float v;
                if (col < 8) {
                    int idx = (t >= 1 && t <= 7 && s >= 8 - t) ? (2 * t + s - 1) : (t + s);
                    v = __ldg(traj + b * TRAJ_BS + idx * DD + col);
                } else {
                    int j = t + s - 8;
                    if (t >= 1 && j >= 0)
                        v = __ldcg(outp + b * OUT_BS + j * OSZ + (col - 8));
                    else
                        v = __ldg(traj + b * TRAJ_BS + (t + s) * DD + col);
                }
                sX[i] = v;
            }
            __syncthreads();

            // init: kh=0 carries bias + x-part; kh=1 starts at zero
            if (kh == 0) {
#pragma unroll
                for (int g = 0; g < 4; ++g) {
                    ull bz = pack2(sB0[ul * 4 + g], 0.f);
#pragma unroll
                    for (int j = 0; j < 4; ++j) acc[g][j] = bz;
                }
                gemm16(acc, sX, sWih0, ul, b0);
            } else {
#pragma unroll
                for (int g = 0; g < 4; ++g)
#pragma unroll
                    for (int j = 0; j < 4; ++j) acc[g][j] = 0ull;
            }

            if (s > 0) {                    // h0_old part (K=256), skipped at s==0
                const float* src = &gH0[p][wg][0][0];
                float4 r[4];
                ldg_chunk(r, src, tid);
#pragma unroll
                for (int c = 0; c < 2; ++c) {
                    __syncthreads();
                    sts_chunk(r, sH, tid);
                    __syncthreads();
                    if (c == 0) ldg_chunk(r, src + 128, tid);
                    gemm64(acc, sH, sWhh0 + c * 8192, ul, b0, kh);
                }
                // fold kh=1 partials into kh=0
                __syncthreads();
                if (kh == 1) {
#pragma unroll
                    for (int g = 0; g < 4; ++g)
#pragma unroll
                        for (int j = 0; j < 4; ++j)
                            sH[(g * 4 + j) * 128 + t128] = sum2(acc[g][j]);
                }
                __syncthreads();
            }
            // cell update layer 0 (kh==0 threads own the state)
            if (kh == 0) {
                float* dstH = &gH0[p ^ 1][wg][0][0];
#pragma unroll
                for (int j = 0; j < 4; ++j) {
                    int b = b0 + j;
                    float gi = sum2(acc[0][j]);
                    float gf = sum2(acc[1][j]);
                    float gG = sum2(acc[2][j]);
                    float gO = sum2(acc[3][j]);
                    if (s > 0) {
                        gi += sH[(0 * 4 + j) * 128 + t128];
                        gf += sH[(1 * 4 + j) * 128 + t128];
                        gG += sH[(2 * 4 + j) * 128 + t128];
                        gO += sH[(3 * 4 + j) * 128 + t128];
                    }
                    float cn = (s ? sigf(gf) * c0s[j] : 0.f) + sigf(gi) * tanhf(gG);
                    c0s[j] = cn;
                    float hn = sigf(gO) * tanhf(cn);
                    __stcg(dstH + b * HH + u, hn);
                    if (t == NWIN - 1 && s == 7) {
                        outp[HN_OFF + b * HH + u] = hn;
                        outp[CN_OFF + b * HH + u] = cn;
                    }
                }
            }
        }
        grid_bar();

        // ---------------- PHASE B: layer-1 cell (+ pred for finishing window) ----
        if (active) {
            if (kh == 0) {
#pragma unroll
                for (int g = 0; g < 4; ++g) {
                    ull bz = pack2(sB1[ul * 4 + g], 0.f);
#pragma unroll
                    for (int j = 0; j < 4; ++j) acc[g][j] = bz;
                }
            } else {
#pragma unroll
                for (int g = 0; g < 4; ++g)
#pragma unroll
                    for (int j = 0; j < 4; ++j) acc[g][j] = 0ull;
            }
            const float* srcA = &gH0[p ^ 1][wg][0][0];  // h0_new (this macro-step)
            const float* srcB = &gH1[p][wg][0][0];      // h1_old
            const int nch = (s > 0) ? 4 : 2;
            float4 r[4];
            ldg_chunk(r, srcA, tid);
            for (int c = 0; c < nch; ++c) {
                __syncthreads();
                sts_chunk(r, sH, tid);
                __syncthreads();
                if (c + 1 < nch) {
                    const float* nsrc = (c + 1 < 2) ? (srcA + (c + 1) * 128)
                                                    : (srcB + (c - 1) * 128);
                    ldg_chunk(r, nsrc, tid);
                }
                const float* wb = (c < 2) ? (sWih1 + c * 8192)
                                          : (sWhh1 + (c - 2) * 8192);
                gemm64(acc, sH, wb, ul, b0, kh);
            }
            // fold kh=1 partials into kh=0
            __syncthreads();
            if (kh == 1) {
#pragma unroll
                for (int g = 0; g < 4; ++g)
#pragma unroll
                    for (int j = 0; j < 4; ++j)
                        sH[(g * 4 + j) * 128 + t128] = sum2(acc[g][j]);
            }
            __syncthreads();

            if (kh == 0) {
                float* dstH = &gH1[p ^ 1][wg][0][0];
#pragma unroll
                for (int j = 0; j < 4; ++j) {
                    int b = b0 + j;
                    float gi = sum2(acc[0][j]) + sH[(0 * 4 + j) * 128 + t128];
                    float gf = sum2(acc[1][j]) + sH[(1 * 4 + j) * 128 + t128];
                    float gG = sum2(acc[2][j]) + sH[(2 * 4 + j) * 128 + t128];
                    float gO = sum2(acc[3][j]) + sH[(3 * 4 + j) * 128 + t128];
                    float cn = (s ? sigf(gf) * c1s[j] : 0.f) + sigf(gi) * tanhf(gG);
                    c1s[j] = cn;
                    float hn = sigf(gO) * tanhf(cn);
                    hn1[j] = hn;
                    __stcg(dstH + b * HH + u, hn);
                    if (t == NWIN - 1 && s == 7) {
                        outp[HN_OFF + BB * HH + b * HH + u] = hn;
                        outp[CN_OFF + BB * HH + b * HH + u] = cn;
                    }
                }
                // finishing window: pred = h1T @ Wlin.T via shfl over ul lanes
                if (s == 7) {
                    float wl[8];
#pragma unroll
                    for (int o = 0; o < 8; ++o) wl[o] = __ldg(Wlin + o * HH + u);
#pragma unroll
                    for (int j = 0; j < 4; ++j) {
#pragma unroll
                        for (int o = 0; o < 8; ++o) {
                            float v = hn1[j] * wl[o];
                            v += __shfl_xor_sync(0xffffffffu, v, 1);
                            v += __shfl_xor_sync(0xffffffffu, v, 2);
                            v += __shfl_xor_sync(0xffffffffu, v, 4);
                            v += __shfl_xor_sync(0xffffffffu, v, 8);
                            if (ul == 0)
                                atomicAdd(outp + (b0 + j) * OUT_BS + t * OSZ + o, v);
                        }
                    }
                }
            }
        }
        grid_bar();
    }
}

extern "C" void kernel_launch(void* const* d_in, const int* in_sizes, int n_in,
                              void* d_out, int out_size)
{
    (void)in_sizes; (void)n_in; (void)out_size;
    const size_t smem_bytes = 54912 * sizeof(float);  // 219648 B
    cudaFuncSetAttribute(orlstm_kernel,
                         cudaFuncAttributeMaxDynamicSharedMemorySize,
                         (int)smem_bytes);
    orlstm_kernel<<<NBLK, NTHR, smem_bytes>>>(
        (const float*)d_in[0],
        (const float*)d_in[1], (const float*)d_in[2],
        (const float*)d_in[3], (const float*)d_in[4],
        (const float*)d_in[5], (const float*)d_in[6],
        (const float*)d_in[7], (const float*)d_in[8],
        (const float*)d_in[9], (const float*)d_in[10],
        (float*)d_out);
}

// round 12
// speedup vs baseline: 2.9477x; 1.0551x over previous
#include <cuda_runtime.h>

#define NBLK 128
#define NTHR 512

#define BB   32
#define TT   128
#define DD   16
#define HH   256
#define OSZ  8
#define NWIN 120
#define NSTEPS 127
#define TRAJ_BS (TT*DD)     /* 2048 */
#define OUT_BS  (NWIN*OSZ)  /* 960  */
#define HN_OFF  30720
#define CN_OFF  47104

typedef unsigned long long ull;

// -------- persistent device state (no allocations allowed) --------
__device__ float gH0[2][8][BB][HH];   // [parity][slot][b][u] layer-0 hidden, ping-pong
__device__ float gH1[2][8][BB][HH];   // layer-1 hidden
__device__ unsigned g_barc = 0;
__device__ volatile unsigned g_barg = 0;

// -------- helpers --------
__device__ __forceinline__ ull pack2(float x, float y) {
    ull r; asm("mov.b64 %0, {%1, %2};" : "=l"(r) : "f"(x), "f"(y)); return r;
}
__device__ __forceinline__ float2 unpack2(ull v) {
    float2 r; asm("mov.b64 {%0, %1}, %2;" : "=f"(r.x), "=f"(r.y) : "l"(v)); return r;
}
__device__ __forceinline__ void fma2(ull& d, ull a, ull b) {
    asm("fma.rn.f32x2 %0, %1, %2, %0;" : "+l"(d) : "l"(a), "l"(b));
}
__device__ __forceinline__ float sigf(float x) { return 1.0f / (1.0f + __expf(-x)); }
__device__ __forceinline__ float sum2(ull v) { float2 f = unpack2(v); return f.x + f.y; }

__device__ __forceinline__ void grid_bar() {
    __threadfence();            // drain global stores to L2
    __syncthreads();
    if (threadIdx.x == 0) {
        unsigned old = g_barg;
        if (atomicAdd(&g_barc, 1u) == NBLK - 1) {
            atomicExch(&g_barc, 0u);
            __threadfence();
            g_barg = old + 1u;
        } else {
            while (g_barg == old) __nanosleep(32);
            __threadfence();
        }
    }
    __syncthreads();
}

// ---- quarter-chunk GEMM (K=32 of a staged 128-chunk). sH: [32][128] row-major.
// sW chunk layout: 64 k2-rows x 128 fl; row r covers k-pair (2r,2r+1);
// within row: (g>>1)*64 + ul*4 + (g&1)*2 holds the f32x2 for (g,u) over that pair.
// kh handles k2-rows [16*kh, 16*kh+16) == K [32*kh, 32*kh+32). ----
__device__ __forceinline__ void gemm32(ull acc[4][4],
                                       const float* __restrict__ sH,
                                       const float* __restrict__ sW,
                                       int ul, int b0, int kh)
{
    const float* hp = sH + b0 * 128 + kh * 32;
    const float* wp = sW + kh * 2048 + ul * 4;
#pragma unroll
    for (int q = 0; q < 8; ++q) {
        ulonglong2 h0 = *(const ulonglong2*)(hp + 0 * 128 + q * 4);
        ulonglong2 h1 = *(const ulonglong2*)(hp + 1 * 128 + q * 4);
        ulonglong2 h2 = *(const ulonglong2*)(hp + 2 * 128 + q * 4);
        ulonglong2 h3 = *(const ulonglong2*)(hp + 3 * 128 + q * 4);
        {
            const float* w = wp + (2 * q) * 128;
            ulonglong2 wA = *(const ulonglong2*)(w);
            ulonglong2 wB = *(const ulonglong2*)(w + 64);
            fma2(acc[0][0], h0.x, wA.x); fma2(acc[0][1], h1.x, wA.x);
            fma2(acc[0][2], h2.x, wA.x); fma2(acc[0][3], h3.x, wA.x);
            fma2(acc[1][0], h0.x, wA.y); fma2(acc[1][1], h1.x, wA.y);
            fma2(acc[1][2], h2.x, wA.y); fma2(acc[1][3], h3.x, wA.y);
            fma2(acc[2][0], h0.x, wB.x); fma2(acc[2][1], h1.x, wB.x);
            fma2(acc[2][2], h2.x, wB.x); fma2(acc[2][3], h3.x, wB.x);
            fma2(acc[3][0], h0.x, wB.y); fma2(acc[3][1], h1.x, wB.y);
            fma2(acc[3][2], h2.x, wB.y); fma2(acc[3][3], h3.x, wB.y);
        }
        {
            const float* w = wp + (2 * q + 1) * 128;
            ulonglong2 wA = *(const ulonglong2*)(w);
            ulonglong2 wB = *(const ulonglong2*)(w + 64);
            fma2(acc[0][0], h0.y, wA.x); fma2(acc[0][1], h1.y, wA.x);
            fma2(acc[0][2], h2.y, wA.x); fma2(acc[0][3], h3.y, wA.x);
            fma2(acc[1][0], h0.y, wA.y); fma2(acc[1][1], h1.y, wA.y);
            fma2(acc[1][2], h2.y, wA.y); fma2(acc[1][3], h3.y, wA.y);
            fma2(acc[2][0], h0.y, wB.x); fma2(acc[2][1], h1.y, wB.x);
            fma2(acc[2][2], h2.y, wB.x); fma2(acc[2][3], h3.y, wB.x);
            fma2(acc[3][0], h0.y, wB.y); fma2(acc[3][1], h1.y, wB.y);
            fma2(acc[3][2], h2.y, wB.y); fma2(acc[3][3], h3.y, wB.y);
        }
    }
}

// K=16 x-part GEMM over sX [32][16] (kh==0 warps only)
__device__ __forceinline__ void gemm16(ull acc[4][4],
                                       const float* __restrict__ sX,
                                       const float* __restrict__ sW,
                                       int ul, int b0)
{
    const float* hp = sX + b0 * 16;
    const float* wp = sW + ul * 4;
#pragma unroll
    for (int q = 0; q < 4; ++q) {
        ulonglong2 h0 = *(const ulonglong2*)(hp + 0 * 16 + q * 4);
        ulonglong2 h1 = *(const ulonglong2*)(hp + 1 * 16 + q * 4);
        ulonglong2 h2 = *(const ulonglong2*)(hp + 2 * 16 + q * 4);
        ulonglong2 h3 = *(const ulonglong2*)(hp + 3 * 16 + q * 4);
#pragma unroll
        for (int e = 0; e < 2; ++e) {
            const float* w = wp + (2 * q + e) * 128;
            ulonglong2 wA = *(const ulonglong2*)(w);
            ulonglong2 wB = *(const ulonglong2*)(w + 64);
            ull v0 = e ? h0.y : h0.x, v1 = e ? h1.y : h1.x;
            ull v2 = e ? h2.y : h2.x, v3 = e ? h3.y : h3.x;
            fma2(acc[0][0], v0, wA.x); fma2(acc[0][1], v1, wA.x);
            fma2(acc[0][2], v2, wA.x); fma2(acc[0][3], v3, wA.x);
            fma2(acc[1][0], v0, wA.y); fma2(acc[1][1], v1, wA.y);
            fma2(acc[1][2], v2, wA.y); fma2(acc[1][3], v3, wA.y);
            fma2(acc[2][0], v0, wB.x); fma2(acc[2][1], v1, wB.x);
            fma2(acc[2][2], v2, wB.x); fma2(acc[2][3], v3, wB.x);
            fma2(acc[3][0], v0, wB.y); fma2(acc[3][1], v1, wB.y);
            fma2(acc[3][2], v2, wB.y); fma2(acc[3][3], v3, wB.y);
        }
    }
}

// Prefetch one 32x128 chunk (global, L2) into registers; store into sH.
__device__ __forceinline__ void ldg_chunk(float4 r[2], const float* __restrict__ src, int tid) {
#pragma unroll
    for (int j = 0; j < 2; ++j) {
        int idx = tid + j * NTHR;
        int b = idx >> 5, q = idx & 31;
        r[j] = __ldcg((const float4*)(src + b * HH) + q);
    }
}
__device__ __forceinline__ void sts_chunk(const float4 r[2], float* __restrict__ sH, int tid) {
#pragma unroll
    for (int j = 0; j < 2; ++j) {
        int idx = tid + j * NTHR;
        *(float4*)(sH + idx * 4) = r[j];
    }
}

// Stage one 64-row x 256-k weight slice into the k-major interleaved layout.
__device__ __forceinline__ void stage_w256(const float* __restrict__ src,
                                           float* __restrict__ dst,
                                           int ubase, int tid)
{
    for (int i = tid; i < 8192; i += NTHR) {
        int r = i >> 7, k2 = i & 127;
        int uu = r >> 2, g = r & 3;
        int grow = g * 256 + ubase + uu;
        float2 w = __ldg((const float2*)(src + grow * 256 + 2 * k2));
        int doff = k2 * 128 + (g >> 1) * 64 + uu * 4 + (g & 1) * 2;
        dst[doff] = w.x; dst[doff + 1] = w.y;
    }
}

__global__ void __launch_bounds__(NTHR, 1)
orlstm_kernel(const float* __restrict__ traj,
              const float* __restrict__ Wih0, const float* __restrict__ Whh0,
              const float* __restrict__ bih0, const float* __restrict__ bhh0,
              const float* __restrict__ Wih1, const float* __restrict__ Whh1,
              const float* __restrict__ bih1, const float* __restrict__ bhh1,
              const float* __restrict__ Wlin, const float* __restrict__ blin,
              float* __restrict__ outp)
{
    extern __shared__ float smem[];
    float* sWhh0 = smem;                    // 128 k2 x 128 = 16384 fl
    float* sWih1 = sWhh0 + 16384;
    float* sWhh1 = sWih1 + 16384;
    float* sWih0 = sWhh1 + 16384;           // 8 k2 x 128 = 1024 fl
    float* sB0   = sWih0 + 1024;            // 64
    float* sB1   = sB0 + 64;                // 64
    float* sX    = sB1 + 64;                // 32 x 16
    float* sH    = sX + 512;                // 32 x 128 = 4096 fl (fold buf kh=1,2)
    float* sF    = sH + 4096;               // 2048 fl (fold buf kh=3)
    // total 56960 floats = 227840 B

    const int tid   = threadIdx.x;
    const int us    = blockIdx.x & 15;      // unit-slice 0..15
    const int wg    = blockIdx.x >> 4;      // window slot 0..7
    const int ubase = us * 16;
    const int ul    = tid & 15;             // local unit 0..15
    const int bq    = (tid >> 4) & 7;       // batch quad 0..7
    const int kh    = tid >> 7;             // k-quarter 0..3
    const int t128  = tid & 127;
    const int b0    = bq * 4;
    const int u     = ubase + ul;

    // ---- one-time weight staging ----
    stage_w256(Whh0, sWhh0, ubase, tid);
    stage_w256(Wih1, sWih1, ubase, tid);
    stage_w256(Whh1, sWhh1, ubase, tid);
    for (int i = tid; i < 512; i += NTHR) {
        int r = i >> 3, k2 = i & 7;
        int uu = r >> 2, g = r & 3;
        int grow = g * 256 + ubase + uu;
        float2 w = __ldg((const float2*)(Wih0 + grow * 16 + 2 * k2));
        int doff = k2 * 128 + (g >> 1) * 64 + uu * 4 + (g & 1) * 2;
        sWih0[doff] = w.x; sWih0[doff + 1] = w.y;
    }
    if (tid < 64) {
        int uu = tid >> 2, g = tid & 3;
        int grow = g * 256 + ubase + uu;
        sB0[uu * 4 + g] = __ldg(bih0 + grow) + __ldg(bhh0 + grow);
        sB1[uu * 4 + g] = __ldg(bih1 + grow) + __ldg(bhh1 + grow);
    }
    __syncthreads();

    float c0s[4] = {0.f, 0.f, 0.f, 0.f};   // cell state (kh==0 threads only)
    float c1s[4] = {0.f, 0.f, 0.f, 0.f};

    for (int k = 0; k < NSTEPS; ++k) {
        const int p = k & 1;
        const int s = (k - wg + 8) & 7;     // this slot's step index at macro-step k
        const int t = k - s;                // window id in this slot
        const bool active = (t >= 0) && (t < NWIN);

        // ---------------- PHASE A: layer-0 cell ----------------
        if (blockIdx.x == 0 && k >= 7 && tid < 256) {
            int tf = k - 7;
            int b = tid >> 3, o = tid & 7;
            float base = (tf == 0)
                ? __ldg(traj + b * TRAJ_BS + 7 * DD + OSZ + o)
                : __ldcg(outp + b * OUT_BS + (tf - 1) * OSZ + o);
            outp[b * OUT_BS + tf * OSZ + o] = base + __ldg(blin + o);
        }

        ull acc[4][4];
        float hn1[4];

        if (active) {
            // build x input [32][16]
            if (tid < 512) {
                int b = tid >> 4, col = tid & 15;
                float v;
                if (col < 8) {
                    int idx = (t >= 1 && t <= 7 && s >= 8 - t) ? (2 * t + s - 1) : (t + s);
                    v = __ldg(traj + b * TRAJ_BS + idx * DD + col);
                } else {
                    int j = t + s - 8;
                    if (t >= 1 && j >= 0)
                        v = __ldcg(outp + b * OUT_BS + j * OSZ + (col - 8));
                    else
                        v = __ldg(traj + b * TRAJ_BS + (t + s) * DD + col);
                }
                sX[tid] = v;
            }
            __syncthreads();

            // init: kh=0 carries bias + x-part; others start at zero
            if (kh == 0) {
#pragma unroll
                for (int g = 0; g < 4; ++g) {
                    ull bz = pack2(sB0[ul * 4 + g], 0.f);
#pragma unroll
                    for (int j = 0; j < 4; ++j) acc[g][j] = bz;
                }
                gemm16(acc, sX, sWih0, ul, b0);
            } else {
#pragma unroll
                for (int g = 0; g < 4; ++g)
#pragma unroll
                    for (int j = 0; j < 4; ++j) acc[g][j] = 0ull;
            }

            if (s > 0) {                    // h0_old part (K=256), skipped at s==0
                const float* src = &gH0[p][wg][0][0];
                float4 r[2];
                ldg_chunk(r, src, tid);
#pragma unroll
                for (int c = 0; c < 2; ++c) {
                    __syncthreads();
                    sts_chunk(r, sH, tid);
                    __syncthreads();
                    if (c == 0) ldg_chunk(r, src + 128, tid);
                    gemm32(acc, sH, sWhh0 + c * 8192, ul, b0, kh);
                }
                // fold kh=1,2,3 partials into kh=0
                __syncthreads();
                if (kh == 1) {
#pragma unroll
                    for (int g = 0; g < 4; ++g)
#pragma unroll
                        for (int j = 0; j < 4; ++j)
                            sH[(g * 4 + j) * 128 + t128] = sum2(acc[g][j]);
                } else if (kh == 2) {
#pragma unroll
                    for (int g = 0; g < 4; ++g)
#pragma unroll
                        for (int j = 0; j < 4; ++j)
                            sH[2048 + (g * 4 + j) * 128 + t128] = sum2(acc[g][j]);
                } else if (kh == 3) {
#pragma unroll
                    for (int g = 0; g < 4; ++g)
#pragma unroll
                        for (int j = 0; j < 4; ++j)
                            sF[(g * 4 + j) * 128 + t128] = sum2(acc[g][j]);
                }
                __syncthreads();
            }
            // cell update layer 0 (kh==0 threads own the state)
            if (kh == 0) {
                float* dstH = &gH0[p ^ 1][wg][0][0];
#pragma unroll
                for (int j = 0; j < 4; ++j) {
                    int b = b0 + j;
                    float gi = sum2(acc[0][j]);
                    float gf = sum2(acc[1][j]);
                    float gG = sum2(acc[2][j]);
                    float gO = sum2(acc[3][j]);
                    if (s > 0) {
                        gi += sH[(0 * 4 + j) * 128 + t128] + sH[2048 + (0 * 4 + j) * 128 + t128] + sF[(0 * 4 + j) * 128 + t128];
                        gf += sH[(1 * 4 + j) * 128 + t128] + sH[2048 + (1 * 4 + j) * 128 + t128] + sF[(1 * 4 + j) * 128 + t128];
                        gG += sH[(2 * 4 + j) * 128 + t128] + sH[2048 + (2 * 4 + j) * 128 + t128] + sF[(2 * 4 + j) * 128 + t128];
                        gO += sH[(3 * 4 + j) * 128 + t128] + sH[2048 + (3 * 4 + j) * 128 + t128] + sF[(3 * 4 + j) * 128 + t128];
                    }
                    float cn = (s ? sigf(gf) * c0s[j] : 0.f) + sigf(gi) * tanhf(gG);
                    c0s[j] = cn;
                    float hn = sigf(gO) * tanhf(cn);
                    __stcg(dstH + b * HH + u, hn);
                    if (t == NWIN - 1 && s == 7) {
                        outp[HN_OFF + b * HH + u] = hn;
                        outp[CN_OFF + b * HH + u] = cn;
                    }
                }
            }
        }
        grid_bar();

        // ---------------- PHASE B: layer-1 cell (+ pred for finishing window) ----
        if (active) {
            if (kh == 0) {
#pragma unroll
                for (int g = 0; g < 4; ++g) {
                    ull bz = pack2(sB1[ul * 4 + g], 0.f);
#pragma unroll
                    for (int j = 0; j < 4; ++j) acc[g][j] = bz;
                }
            } else {
#pragma unroll
                for (int g = 0; g < 4; ++g)
#pragma unroll
                    for (int j = 0; j < 4; ++j) acc[g][j] = 0ull;
            }
            const float* srcA = &gH0[p ^ 1][wg][0][0];  // h0_new (this macro-step)
            const float* srcB = &gH1[p][wg][0][0];      // h1_old
            const int nch = (s > 0) ? 4 : 2;
            float4 r[2];
            ldg_chunk(r, srcA, tid);
            for (int c = 0; c < nch; ++c) {
                __syncthreads();
                sts_chunk(r, sH, tid);
                __syncthreads();
                if (c + 1 < nch) {
                    const float* nsrc = (c + 1 < 2) ? (srcA + (c + 1) * 128)
                                                    : (srcB + (c - 1) * 128);
                    ldg_chunk(r, nsrc, tid);
                }
                const float* wb = (c < 2) ? (sWih1 + c * 8192)
                                          : (sWhh1 + (c - 2) * 8192);
                gemm32(acc, sH, wb, ul, b0, kh);
            }
            // fold kh=1,2,3 partials into kh=0
            __syncthreads();
            if (kh == 1) {
#pragma unroll
                for (int g = 0; g < 4; ++g)
#pragma unroll
                    for (int j = 0; j < 4; ++j)
                        sH[(g * 4 + j) * 128 + t128] = sum2(acc[g][j]);
            } else if (kh == 2) {
#pragma unroll
                for (int g = 0; g < 4; ++g)
#pragma unroll
                    for (int j = 0; j < 4; ++j)
                        sH[2048 + (g * 4 + j) * 128 + t128] = sum2(acc[g][j]);
            } else if (kh == 3) {
#pragma unroll
                for (int g = 0; g < 4; ++g)
#pragma unroll
                    for (int j = 0; j < 4; ++j)
                        sF[(g * 4 + j) * 128 + t128] = sum2(acc[g][j]);
            }
            __syncthreads();

            if (kh == 0) {
                float* dstH = &gH1[p ^ 1][wg][0][0];
#pragma unroll
                for (int j = 0; j < 4; ++j) {
                    int b = b0 + j;
                    float gi = sum2(acc[0][j]) + sH[(0 * 4 + j) * 128 + t128] + sH[2048 + (0 * 4 + j) * 128 + t128] + sF[(0 * 4 + j) * 128 + t128];
                    float gf = sum2(acc[1][j]) + sH[(1 * 4 + j) * 128 + t128] + sH[2048 + (1 * 4 + j) * 128 + t128] + sF[(1 * 4 + j) * 128 + t128];
                    float gG = sum2(acc[2][j]) + sH[(2 * 4 + j) * 128 + t128] + sH[2048 + (2 * 4 + j) * 128 + t128] + sF[(2 * 4 + j) * 128 + t128];
                    float gO = sum2(acc[3][j]) + sH[(3 * 4 + j) * 128 + t128] + sH[2048 + (3 * 4 + j) * 128 + t128] + sF[(3 * 4 + j) * 128 + t128];
                    float cn = (s ? sigf(gf) * c1s[j] : 0.f) + sigf(gi) * tanhf(gG);
                    c1s[j] = cn;
                    float hn = sigf(gO) * tanhf(cn);
                    hn1[j] = hn;
                    __stcg(dstH + b * HH + u, hn);
                    if (t == NWIN - 1 && s == 7) {
                        outp[HN_OFF + BB * HH + b * HH + u] = hn;
                        outp[CN_OFF + BB * HH + b * HH + u] = cn;
                    }
                }
                // finishing window: pred = h1T @ Wlin.T via shfl over ul lanes
                if (s == 7) {
                    float wl[8];
#pragma unroll
                    for (int o = 0; o < 8; ++o) wl[o] = __ldg(Wlin + o * HH + u);
#pragma unroll
                    for (int j = 0; j < 4; ++j) {
#pragma unroll
                        for (int o = 0; o < 8; ++o) {
                            float v = hn1[j] * wl[o];
                            v += __shfl_xor_sync(0xffffffffu, v, 1);
                            v += __shfl_xor_sync(0xffffffffu, v, 2);
                            v += __shfl_xor_sync(0xffffffffu, v, 4);
                            v += __shfl_xor_sync(0xffffffffu, v, 8);
                            if (ul == 0)
                                atomicAdd(outp + (b0 + j) * OUT_BS + t * OSZ + o, v);
                        }
                    }
                }
            }
        }
        grid_bar();
    }
}

extern "C" void kernel_launch(void* const* d_in, const int* in_sizes, int n_in,
                              void* d_out, int out_size)
{
    (void)in_sizes; (void)n_in; (void)out_size;
    const size_t smem_bytes = 56960 * sizeof(float);  // 227840 B
    cudaFuncSetAttribute(orlstm_kernel,
                         cudaFuncAttributeMaxDynamicSharedMemorySize,
                         (int)smem_bytes);
    orlstm_kernel<<<NBLK, NTHR, smem_bytes>>>(
        (const float*)d_in[0],
        (const float*)d_in[1], (const float*)d_in[2],
        (const float*)d_in[3], (const float*)d_in[4],
        (const float*)d_in[5], (const float*)d_in[6],
        (const float*)d_in[7], (const float*)d_in[8],
        (const float*)d_in[9], (const float*)d_in[10],
        (float*)d_out);
}

// round 13
// speedup vs baseline: 2.9952x; 1.0161x over previous
#include <cuda_runtime.h>

#define NBLK 128
#define NTHR 512

#define BB   32
#define TT   128
#define DD   16
#define HH   256
#define OSZ  8
#define NWIN 120
#define NSTEPS 127
#define TRAJ_BS (TT*DD)     /* 2048 */
#define OUT_BS  (NWIN*OSZ)  /* 960  */
#define HN_OFF  30720
#define CN_OFF  47104

typedef unsigned long long ull;

// -------- persistent device state (no allocations allowed) --------
__device__ float gH0[2][8][BB][HH];   // [parity][slot][b][u] layer-0 hidden, ping-pong
__device__ float gH1[2][8][BB][HH];   // layer-1 hidden
__device__ unsigned g_barc = 0;       // final global barrier
__device__ volatile unsigned g_barg = 0;
__device__ unsigned g_gc[8];          // per-group barrier counters
__device__ volatile unsigned g_gg[8]; // per-group generations (monotonic across replays)
__device__ unsigned g_outcnt[NWIN];   // per-window completion counters (reset at kernel end)

// -------- helpers --------
__device__ __forceinline__ ull pack2(float x, float y) {
    ull r; asm("mov.b64 %0, {%1, %2};" : "=l"(r) : "f"(x), "f"(y)); return r;
}
__device__ __forceinline__ float2 unpack2(ull v) {
    float2 r; asm("mov.b64 {%0, %1}, %2;" : "=f"(r.x), "=f"(r.y) : "l"(v)); return r;
}
__device__ __forceinline__ void fma2(ull& d, ull a, ull b) {
    asm("fma.rn.f32x2 %0, %1, %2, %0;" : "+l"(d) : "l"(a), "l"(b));
}
__device__ __forceinline__ float sigf(float x) { return 1.0f / (1.0f + __expf(-x)); }
__device__ __forceinline__ float sum2(ull v) { float2 f = unpack2(v); return f.x + f.y; }

// 16-CTA group barrier (only CTAs sharing wg exchange h-state)
__device__ __forceinline__ void group_bar(int wg) {
    __threadfence();            // drain this CTA's global stores to L2
    __syncthreads();
    if (threadIdx.x == 0) {
        unsigned old = g_gg[wg];
        if (atomicAdd(&g_gc[wg], 1u) == 15u) {
            atomicExch(&g_gc[wg], 0u);
            __threadfence();
            g_gg[wg] = old + 1u;
        } else {
            while (g_gg[wg] == old) { }
            __threadfence();
        }
    }
    __syncthreads();
}

// final global barrier (used once, for replay-safe counter reset)
__device__ __forceinline__ void grid_bar_global() {
    __threadfence();
    __syncthreads();
    if (threadIdx.x == 0) {
        unsigned old = g_barg;
        if (atomicAdd(&g_barc, 1u) == NBLK - 1) {
            atomicExch(&g_barc, 0u);
            __threadfence();
            g_barg = old + 1u;
        } else {
            while (g_barg == old) __nanosleep(32);
            __threadfence();
        }
    }
    __syncthreads();
}

// ---- quarter-chunk GEMM (K=32 of a staged 128-chunk). sH: [32][128] row-major.
// sW chunk layout: 64 k2-rows x 128 fl; row r covers k-pair (2r,2r+1);
// within row: (g>>1)*64 + ul*4 + (g&1)*2 holds the f32x2 for (g,u) over that pair.
__device__ __forceinline__ void gemm32(ull acc[4][4],
                                       const float* __restrict__ sH,
                                       const float* __restrict__ sW,
                                       int ul, int b0, int kh)
{
    const float* hp = sH + b0 * 128 + kh * 32;
    const float* wp = sW + kh * 2048 + ul * 4;
#pragma unroll
    for (int q = 0; q < 8; ++q) {
        ulonglong2 h0 = *(const ulonglong2*)(hp + 0 * 128 + q * 4);
        ulonglong2 h1 = *(const ulonglong2*)(hp + 1 * 128 + q * 4);
        ulonglong2 h2 = *(const ulonglong2*)(hp + 2 * 128 + q * 4);
        ulonglong2 h3 = *(const ulonglong2*)(hp + 3 * 128 + q * 4);
        {
            const float* w = wp + (2 * q) * 128;
            ulonglong2 wA = *(const ulonglong2*)(w);
            ulonglong2 wB = *(const ulonglong2*)(w + 64);
            fma2(acc[0][0], h0.x, wA.x); fma2(acc[0][1], h1.x, wA.x);
            fma2(acc[0][2], h2.x, wA.x); fma2(acc[0][3], h3.x, wA.x);
            fma2(acc[1][0], h0.x, wA.y); fma2(acc[1][1], h1.x, wA.y);
            fma2(acc[1][2], h2.x, wA.y); fma2(acc[1][3], h3.x, wA.y);
            fma2(acc[2][0], h0.x, wB.x); fma2(acc[2][1], h1.x, wB.x);
            fma2(acc[2][2], h2.x, wB.x); fma2(acc[2][3], h3.x, wB.x);
            fma2(acc[3][0], h0.x, wB.y); fma2(acc[3][1], h1.x, wB.y);
            fma2(acc[3][2], h2.x, wB.y); fma2(acc[3][3], h3.x, wB.y);
        }
        {
            const float* w = wp + (2 * q + 1) * 128;
            ulonglong2 wA = *(const ulonglong2*)(w);
            ulonglong2 wB = *(const ulonglong2*)(w + 64);
            fma2(acc[0][0], h0.y, wA.x); fma2(acc[0][1], h1.y, wA.x);
            fma2(acc[0][2], h2.y, wA.x); fma2(acc[0][3], h3.y, wA.x);
            fma2(acc[1][0], h0.y, wA.y); fma2(acc[1][1], h1.y, wA.y);
            fma2(acc[1][2], h2.y, wA.y); fma2(acc[1][3], h3.y, wA.y);
            fma2(acc[2][0], h0.y, wB.x); fma2(acc[2][1], h1.y, wB.x);
            fma2(acc[2][2], h2.y, wB.x); fma2(acc[2][3], h3.y, wB.x);
            fma2(acc[3][0], h0.y, wB.y); fma2(acc[3][1], h1.y, wB.y);
            fma2(acc[3][2], h2.y, wB.y); fma2(acc[3][3], h3.y, wB.y);
        }
    }
}

// K=16 x-part GEMM over sX [32][16] (kh==0 warps only)
__device__ __forceinline__ void gemm16(ull acc[4][4],
                                       const float* __restrict__ sX,
                                       const float* __restrict__ sW,
                                       int ul, int b0)
{
    const float* hp = sX + b0 * 16;
    const float* wp = sW + ul * 4;
#pragma unroll
    for (int q = 0; q < 4; ++q) {
        ulonglong2 h0 = *(const ulonglong2*)(hp + 0 * 16 + q * 4);
        ulonglong2 h1 = *(const ulonglong2*)(hp + 1 * 16 + q * 4);
        ulonglong2 h2 = *(const ulonglong2*)(hp + 2 * 16 + q * 4);
        ulonglong2 h3 = *(const ulonglong2*)(hp + 3 * 16 + q * 4);
#pragma unroll
        for (int e = 0; e < 2; ++e) {
            const float* w = wp + (2 * q + e) * 128;
            ulonglong2 wA = *(const ulonglong2*)(w);
            ulonglong2 wB = *(const ulonglong2*)(w + 64);
            ull v0 = e ? h0.y : h0.x, v1 = e ? h1.y : h1.x;
            ull v2 = e ? h2.y : h2.x, v3 = e ? h3.y : h3.x;
            fma2(acc[0][0], v0, wA.x); fma2(acc[0][1], v1, wA.x);
            fma2(acc[0][2], v2, wA.x); fma2(acc[0][3], v3, wA.x);
            fma2(acc[1][0], v0, wA.y); fma2(acc[1][1], v1, wA.y);
            fma2(acc[1][2], v2, wA.y); fma2(acc[1][3], v3, wA.y);
            fma2(acc[2][0], v0, wB.x); fma2(acc[2][1], v1, wB.x);
            fma2(acc[2][2], v2, wB.x); fma2(acc[2][3], v3, wB.x);
            fma2(acc[3][0], v0, wB.y); fma2(acc[3][1], v1, wB.y);
            fma2(acc[3][2], v2, wB.y); fma2(acc[3][3], v3, wB.y);
        }
    }
}

__device__ __forceinline__ void ldg_chunk(float4 r[2], const float* __restrict__ src, int tid) {
#pragma unroll
    for (int j = 0; j < 2; ++j) {
        int idx = tid + j * NTHR;
        int b = idx >> 5, q = idx & 31;
        r[j] = __ldcg((const float4*)(src + b * HH) + q);
    }
}
__device__ __forceinline__ void sts_chunk(const float4 r[2], float* __restrict__ sH, int tid) {
#pragma unroll
    for (int j = 0; j < 2; ++j) {
        int idx = tid + j * NTHR;
        *(float4*)(sH + idx * 4) = r[j];
    }
}

__device__ __forceinline__ void stage_w256(const float* __restrict__ src,
                                           float* __restrict__ dst,
                                           int ubase, int tid)
{
    for (int i = tid; i < 8192; i += NTHR) {
        int r = i >> 7, k2 = i & 127;
        int uu = r >> 2, g = r & 3;
        int grow = g * 256 + ubase + uu;
        float2 w = __ldg((const float2*)(src + grow * 256 + 2 * k2));
        int doff = k2 * 128 + (g >> 1) * 64 + uu * 4 + (g & 1) * 2;
        dst[doff] = w.x; dst[doff + 1] = w.y;
    }
}

__global__ void __launch_bounds__(NTHR, 1)
orlstm_kernel(const float* __restrict__ traj,
              const float* __restrict__ Wih0, const float* __restrict__ Whh0,
              const float* __restrict__ bih0, const float* __restrict__ bhh0,
              const float* __restrict__ Wih1, const float* __restrict__ Whh1,
              const float* __restrict__ bih1, const float* __restrict__ bhh1,
              const float* __restrict__ Wlin, const float* __restrict__ blin,
              float* __restrict__ outp)
{
    extern __shared__ float smem[];
    float* sWhh0 = smem;                    // 128 k2 x 128 = 16384 fl
    float* sWih1 = sWhh0 + 16384;
    float* sWhh1 = sWih1 + 16384;
    float* sWih0 = sWhh1 + 16384;           // 1024 fl
    float* sB0   = sWih0 + 1024;            // 64
    float* sB1   = sB0 + 64;                // 64
    float* sX    = sB1 + 64;                // 512
    float* sH    = sX + 512;                // 4096 fl (fold buf kh=1,2)
    float* sF    = sH + 4096;               // 2048 fl (fold buf kh=3)

    const int tid   = threadIdx.x;
    const int us    = blockIdx.x & 15;      // unit-slice 0..15
    const int wg    = blockIdx.x >> 4;      // window slot 0..7
    const int ubase = us * 16;
    const int ul    = tid & 15;
    const int bq    = (tid >> 4) & 7;
    const int kh    = tid >> 7;
    const int t128  = tid & 127;
    const int b0    = bq * 4;
    const int u     = ubase + ul;

    // ---- one-time weight staging ----
    stage_w256(Whh0, sWhh0, ubase, tid);
    stage_w256(Wih1, sWih1, ubase, tid);
    stage_w256(Whh1, sWhh1, ubase, tid);
    for (int i = tid; i < 512; i += NTHR) {
        int r = i >> 3, k2 = i & 7;
        int uu = r >> 2, g = r & 3;
        int grow = g * 256 + ubase + uu;
        float2 w = __ldg((const float2*)(Wih0 + grow * 16 + 2 * k2));
        int doff = k2 * 128 + (g >> 1) * 64 + uu * 4 + (g & 1) * 2;
        sWih0[doff] = w.x; sWih0[doff + 1] = w.y;
    }
    if (tid < 64) {
        int uu = tid >> 2, g = tid & 3;
        int grow = g * 256 + ubase + uu;
        sB0[uu * 4 + g] = __ldg(bih0 + grow) + __ldg(bhh0 + grow);
        sB1[uu * 4 + g] = __ldg(bih1 + grow) + __ldg(bhh1 + grow);
    }
    __syncthreads();

    float c0s[4] = {0.f, 0.f, 0.f, 0.f};
    float c1s[4] = {0.f, 0.f, 0.f, 0.f};

    volatile unsigned* vcnt = (volatile unsigned*)g_outcnt;

    for (int k = 0; k < NSTEPS; ++k) {
        const int p = k & 1;
        const int s = (k - wg + 8) & 7;
        const int t = k - s;
        const bool active = (t >= 0) && (t < NWIN);

        ull acc[4][4];
        float hn1[4];

        // ---------------- PHASE A: layer-0 cell ----------------
        if (active) {
            // zero this window's out slot at window start (slack: consumed at t+7)
            if (s == 0 && us == 0 && tid < 256) {
                int b = tid >> 3, o = tid & 7;
                __stcg(outp + b * OUT_BS + t * OSZ + o, 0.f);
            }
            // wait for out[j] of the window this step's x depends on (usually ready)
            {
                int jj = t + s - 8;
                if (t >= 1 && jj >= 0 && tid == 0) {
                    while (vcnt[jj] < 16u) { }
                    __threadfence();
                }
            }
            __syncthreads();

            // build x input [32][16]
            if (tid < 512) {
                int b = tid >> 4, col = tid & 15;
                float v;
                if (col < 8) {
                    int idx = (t >= 1 && t <= 7 && s >= 8 - t) ? (2 * t + s - 1) : (t + s);
                    v = __ldg(traj + b * TRAJ_BS + idx * DD + col);
                } else {
                    int j = t + s - 8;
                    if (t >= 1 && j >= 0)
                        v = __ldcg(outp + b * OUT_BS + j * OSZ + (col - 8));
                    else
                        v = __ldg(traj + b * TRAJ_BS + (t + s) * DD + col);
                }
                sX[tid] = v;
            }
            __syncthreads();

            if (kh == 0) {
#pragma unroll
                for (int g = 0; g < 4; ++g) {
                    ull bz = pack2(sB0[ul * 4 + g], 0.f);
#pragma unroll
                    for (int j = 0; j < 4; ++j) acc[g][j] = bz;
                }
                gemm16(acc, sX, sWih0, ul, b0);
            } else {
#pragma unroll
                for (int g = 0; g < 4; ++g)
#pragma unroll
                    for (int j = 0; j < 4; ++j) acc[g][j] = 0ull;
            }

            if (s > 0) {
                const float* src = &gH0[p][wg][0][0];
                float4 r[2];
                ldg_chunk(r, src, tid);
#pragma unroll
                for (int c = 0; c < 2; ++c) {
                    __syncthreads();
                    sts_chunk(r, sH, tid);
                    __syncthreads();
                    if (c == 0) ldg_chunk(r, src + 128, tid);
                    gemm32(acc, sH, sWhh0 + c * 8192, ul, b0, kh);
                }
                __syncthreads();
                if (kh == 1) {
#pragma unroll
                    for (int g = 0; g < 4; ++g)
#pragma unroll
                        for (int j = 0; j < 4; ++j)
                            sH[(g * 4 + j) * 128 + t128] = sum2(acc[g][j]);
                } else if (kh == 2) {
#pragma unroll
                    for (int g = 0; g < 4; ++g)
#pragma unroll
                        for (int j = 0; j < 4; ++j)
                            sH[2048 + (g * 4 + j) * 128 + t128] = sum2(acc[g][j]);
                } else if (kh == 3) {
#pragma unroll
                    for (int g = 0; g < 4; ++g)
#pragma unroll
                        for (int j = 0; j < 4; ++j)
                            sF[(g * 4 + j) * 128 + t128] = sum2(acc[g][j]);
                }
                __syncthreads();
            }
            if (kh == 0) {
                float* dstH = &gH0[p ^ 1][wg][0][0];
#pragma unroll
                for (int j = 0; j < 4; ++j) {
                    int b = b0 + j;
                    float gi = sum2(acc[0][j]);
                    float gf = sum2(acc[1][j]);
                    float gG = sum2(acc[2][j]);
                    float gO = sum2(acc[3][j]);
                    if (s > 0) {
                        gi += sH[(0 * 4 + j) * 128 + t128] + sH[2048 + (0 * 4 + j) * 128 + t128] + sF[(0 * 4 + j) * 128 + t128];
                        gf += sH[(1 * 4 + j) * 128 + t128] + sH[2048 + (1 * 4 + j) * 128 + t128] + sF[(1 * 4 + j) * 128 + t128];
                        gG += sH[(2 * 4 + j) * 128 + t128] + sH[2048 + (2 * 4 + j) * 128 + t128] + sF[(2 * 4 + j) * 128 + t128];
                        gO += sH[(3 * 4 + j) * 128 + t128] + sH[2048 + (3 * 4 + j) * 128 + t128] + sF[(3 * 4 + j) * 128 + t128];
                    }
                    float cn = (s ? sigf(gf) * c0s[j] : 0.f) + sigf(gi) * tanhf(gG);
                    c0s[j] = cn;
                    float hn = sigf(gO) * tanhf(cn);
                    __stcg(dstH + b * HH + u, hn);
                    if (t == NWIN - 1 && s == 7) {
                        outp[HN_OFF + b * HH + u] = hn;
                        outp[CN_OFF + b * HH + u] = cn;
                    }
                }
            }
        }
        group_bar(wg);

        // ---------------- PHASE B: layer-1 cell (+ pred for finishing window) ----
        if (active) {
            if (kh == 0) {
#pragma unroll
                for (int g = 0; g < 4; ++g) {
                    ull bz = pack2(sB1[ul * 4 + g], 0.f);
#pragma unroll
                    for (int j = 0; j < 4; ++j) acc[g][j] = bz;
                }
            } else {
#pragma unroll
                for (int g = 0; g < 4; ++g)
#pragma unroll
                    for (int j = 0; j < 4; ++j) acc[g][j] = 0ull;
            }
            const float* srcA = &gH0[p ^ 1][wg][0][0];
            const float* srcB = &gH1[p][wg][0][0];
            const int nch = (s > 0) ? 4 : 2;
            float4 r[2];
            ldg_chunk(r, srcA, tid);
            for (int c = 0; c < nch; ++c) {
                __syncthreads();
                sts_chunk(r, sH, tid);
                __syncthreads();
                if (c + 1 < nch) {
                    const float* nsrc = (c + 1 < 2) ? (srcA + (c + 1) * 128)
                                                    : (srcB + (c - 1) * 128);
                    ldg_chunk(r, nsrc, tid);
                }
                const float* wb = (c < 2) ? (sWih1 + c * 8192)
                                          : (sWhh1 + (c - 2) * 8192);
                gemm32(acc, sH, wb, ul, b0, kh);
            }
            __syncthreads();
            if (kh == 1) {
#pragma unroll
                for (int g = 0; g < 4; ++g)
#pragma unroll
                    for (int j = 0; j < 4; ++j)
                        sH[(g * 4 + j) * 128 + t128] = sum2(acc[g][j]);
            } else if (kh == 2) {
#pragma unroll
                for (int g = 0; g < 4; ++g)
#pragma unroll
                    for (int j = 0; j < 4; ++j)
                        sH[2048 + (g * 4 + j) * 128 + t128] = sum2(acc[g][j]);
            } else if (kh == 3) {
#pragma unroll
                for (int g = 0; g < 4; ++g)
#pragma unroll
                    for (int j = 0; j < 4; ++j)
                        sF[(g * 4 + j) * 128 + t128] = sum2(acc[g][j]);
            }
            __syncthreads();

            if (kh == 0) {
                float* dstH = &gH1[p ^ 1][wg][0][0];
#pragma unroll
                for (int j = 0; j < 4; ++j) {
                    int b = b0 + j;
                    float gi = sum2(acc[0][j]) + sH[(0 * 4 + j) * 128 + t128] + sH[2048 + (0 * 4 + j) * 128 + t128] + sF[(0 * 4 + j) * 128 + t128];
                    float gf = sum2(acc[1][j]) + sH[(1 * 4 + j) * 128 + t128] + sH[2048 + (1 * 4 + j) * 128 + t128] + sF[(1 * 4 + j) * 128 + t128];
                    float gG = sum2(acc[2][j]) + sH[(2 * 4 + j) * 128 + t128] + sH[2048 + (2 * 4 + j) * 128 + t128] + sF[(2 * 4 + j) * 128 + t128];
                    float gO = sum2(acc[3][j]) + sH[(3 * 4 + j) * 128 + t128] + sH[2048 + (3 * 4 + j) * 128 + t128] + sF[(3 * 4 + j) * 128 + t128];
                    float cn = (s ? sigf(gf) * c1s[j] : 0.f) + sigf(gi) * tanhf(gG);
                    c1s[j] = cn;
                    float hn = sigf(gO) * tanhf(cn);
                    hn1[j] = hn;
                    __stcg(dstH + b * HH + u, hn);
                    if (t == NWIN - 1 && s == 7) {
                        outp[HN_OFF + BB * HH + b * HH + u] = hn;
                        outp[CN_OFF + BB * HH + b * HH + u] = cn;
                    }
                }
                if (s == 7) {
                    float wl[8];
#pragma unroll
                    for (int o = 0; o < 8; ++o) wl[o] = __ldg(Wlin + o * HH + u);
#pragma unroll
                    for (int j = 0; j < 4; ++j) {
#pragma unroll
                        for (int o = 0; o < 8; ++o) {
                            float v = hn1[j] * wl[o];
                            v += __shfl_xor_sync(0xffffffffu, v, 1);
                            v += __shfl_xor_sync(0xffffffffu, v, 2);
                            v += __shfl_xor_sync(0xffffffffu, v, 4);
                            v += __shfl_xor_sync(0xffffffffu, v, 8);
                            if (ul == 0)
                                atomicAdd(outp + (b0 + j) * OUT_BS + t * OSZ + o, v);
                        }
                    }
                }
            }
            // finishing window: us==0 CTA adds the base (out[t-1] + b_lin)
            if (s == 7) {
                if (us == 0 && tid < 256) {
                    int b = tid >> 3, o = tid & 7;
                    float base;
                    if (t == 0) {
                        base = __ldg(traj + b * TRAJ_BS + 7 * DD + OSZ + o);
                    } else {
                        while (vcnt[t - 1] < 16u) { }
                        __threadfence();
                        base = __ldcg(outp + b * OUT_BS + (t - 1) * OSZ + o);
                    }
                    atomicAdd(outp + b * OUT_BS + t * OSZ + o, base + __ldg(blin + o));
                }
                __syncthreads();
                if (tid == 0) {
                    __threadfence();
                    atomicAdd(&g_outcnt[t], 1u);   // release: this CTA's contributions done
                }
            }
        }
        group_bar(wg);
    }

    // replay-safe reset of per-window counters
    grid_bar_global();
    if (blockIdx.x == 0) {
        for (int i = tid; i < NWIN; i += NTHR) g_outcnt[i] = 0u;
    }
}

extern "C" void kernel_launch(void* const* d_in, const int* in_sizes, int n_in,
                              void* d_out, int out_size)
{
    (void)in_sizes; (void)n_in; (void)out_size;
    const size_t smem_bytes = 56960 * sizeof(float);  // 227840 B
    cudaFuncSetAttribute(orlstm_kernel,
                         cudaFuncAttributeMaxDynamicSharedMemorySize,
                         (int)smem_bytes);
    orlstm_kernel<<<NBLK, NTHR, smem_bytes>>>(
        (const float*)d_in[0],
        (const float*)d_in[1], (const float*)d_in[2],
        (const float*)d_in[3], (const float*)d_in[4],
        (const float*)d_in[5], (const float*)d_in[6],
        (const float*)d_in[7], (const float*)d_in[8],
        (const float*)d_in[9], (const float*)d_in[10],
        (float*)d_out);
}